// round 4
// baseline (speedup 1.0000x reference)
#include <cuda_runtime.h>

// Maxwell viscoelastic model, warp-parallel affine scan, 256 elems/warp-iter,
// fully-coalesced accesses via two contiguous 4-elem segments per lane.
//
//   gamma_{t+1} = A_t*gamma_t + B_t,  A_t = 1-2*dt_t, B_t = 2*dt_t*eps_t
//   out_0 = 0 ; out_t = eps_t + 2*(eps_t - gamma_t)
//
// Iteration covers 256 timesteps = segment a (t 0..127) then segment b
// (t 128..255). Lane l owns t=[4l,4l+3] in EACH segment, so every float4
// load/store is warp-coalesced (4 full 128B lines per instruction).
// Two independent 5-round Kogge-Stone scans (one per segment) are
// interleaved for SHFL-latency overlap; segment-b prefixes compose through
// segment-a's full product. Streaming cache hints (touch-once data).

#define TT   2048
#define EPI  256
#define NITER (TT / EPI)               // 8
#define WARPS_PER_BLOCK 8
#define NTHREADS (WARPS_PER_BLOCK * 32)

__global__ __launch_bounds__(NTHREADS, 4)
void maxwell_warp_scan_v3(const float* __restrict__ eps_g,
                          const float* __restrict__ dt_g,
                          float* __restrict__ out_g) {
    const int lane = threadIdx.x & 31;
    const int warp = threadIdx.x >> 5;
    const int row  = blockIdx.x * WARPS_PER_BLOCK + warp;
    const size_t base = (size_t)row * TT;

    const float4* eps4 = reinterpret_cast<const float4*>(eps_g + base);
    const float4* dt4  = reinterpret_cast<const float4*>(dt_g  + base);
    float4*       out4 = reinterpret_cast<float4*>(out_g + base);

    float gamma_in = 0.0f;

    // Prefetch iteration 0 (all coalesced: lane-stride = 1 float4).
    float4 ea = __ldcs(&eps4[lane]);
    float4 eb = __ldcs(&eps4[lane + 32]);
    float4 da = __ldcs(&dt4[lane]);
    float4 db = __ldcs(&dt4[lane + 32]);

#pragma unroll 1
    for (int it = 0; it < NITER; ++it) {
        // Prefetch next iteration; stays in flight across both scan chains.
        float4 ean, ebn, dan, dbn;
        if (it + 1 < NITER) {
            const int qn = (it + 1) * 64 + lane;
            ean = __ldcs(&eps4[qn]);
            ebn = __ldcs(&eps4[qn + 32]);
            dan = __ldcs(&dt4[qn]);
            dbn = __ldcs(&dt4[qn + 32]);
        }

        const float tda[4] = {da.x + da.x, da.y + da.y, da.z + da.z, da.w + da.w};
        const float tdb[4] = {db.x + db.x, db.y + db.y, db.z + db.z, db.w + db.w};
        const float eea[4] = {ea.x, ea.y, ea.z, ea.w};
        const float eeb[4] = {eb.x, eb.y, eb.z, eb.w};

        // Lane-local compose of 4 maps per segment (two independent chains).
        float Aa = 1.0f - tda[0], Ba = tda[0] * eea[0];
        float Ab = 1.0f - tdb[0], Bb = tdb[0] * eeb[0];
#pragma unroll
        for (int k = 1; k < 4; ++k) {
            const float Aka = 1.0f - tda[k], Bka = tda[k] * eea[k];
            Ba = fmaf(Aka, Ba, Bka);  Aa = Aka * Aa;
            const float Akb = 1.0f - tdb[k], Bkb = tdb[k] * eeb[k];
            Bb = fmaf(Akb, Bb, Bkb);  Ab = Akb * Ab;
        }

        // Two interleaved inclusive Kogge-Stone scans (independent chains).
        float SAa = Aa, SBa = Ba, SAb = Ab, SBb = Bb;
#pragma unroll
        for (int dstep = 1; dstep < 32; dstep <<= 1) {
            const float pAa = __shfl_up_sync(0xffffffffu, SAa, dstep);
            const float pBa = __shfl_up_sync(0xffffffffu, SBa, dstep);
            const float pAb = __shfl_up_sync(0xffffffffu, SAb, dstep);
            const float pBb = __shfl_up_sync(0xffffffffu, SBb, dstep);
            if (lane >= dstep) {
                SBa = fmaf(SAa, pBa, SBa);  SAa = SAa * pAa;
                SBb = fmaf(SAb, pBb, SBb);  SAb = SAb * pAb;
            }
        }

        // Exclusive prefixes (identity on lane 0) and full products.
        float EAa = __shfl_up_sync(0xffffffffu, SAa, 1);
        float EBa = __shfl_up_sync(0xffffffffu, SBa, 1);
        float EAb = __shfl_up_sync(0xffffffffu, SAb, 1);
        float EBb = __shfl_up_sync(0xffffffffu, SBb, 1);
        if (lane == 0) { EAa = 1.0f; EBa = 0.0f; EAb = 1.0f; EBb = 0.0f; }
        const float PAa = __shfl_sync(0xffffffffu, SAa, 31);
        const float PBa = __shfl_sync(0xffffffffu, SBa, 31);
        const float PAb = __shfl_sync(0xffffffffu, SAb, 31);
        const float PBb = __shfl_sync(0xffffffffu, SBb, 31);

        // Entry gammas: segment a from gamma_in; segment b through gmid.
        float gA = fmaf(EAa, gamma_in, EBa);
        const float gmid = fmaf(PAa, gamma_in, PBa);
        float gB = fmaf(EAb, gmid, EBb);

        // Apply: t = eps-gamma; sigma = eps + 2t; gamma += 2dt*t.
        float sa[4], sb[4];
#pragma unroll
        for (int k = 0; k < 4; ++k) {
            const float ta = eea[k] - gA;
            sa[k] = fmaf(2.0f, ta, eea[k]);
            gA = fmaf(tda[k], ta, gA);
            const float tb = eeb[k] - gB;
            sb[k] = fmaf(2.0f, tb, eeb[k]);
            gB = fmaf(tdb[k], tb, gB);
        }

        if (it == 0 && lane == 0) sa[0] = 0.0f;   // out[0] = 0

        const int qo = it * 64 + lane;
        __stcs(&out4[qo],      make_float4(sa[0], sa[1], sa[2], sa[3]));
        __stcs(&out4[qo + 32], make_float4(sb[0], sb[1], sb[2], sb[3]));

        // Warp-wide carry across 256 elements.
        gamma_in = fmaf(PAb, gmid, PBb);

        if (it + 1 < NITER) { ea = ean; eb = ebn; da = dan; db = dbn; }
    }
}

extern "C" void kernel_launch(void* const* d_in, const int* in_sizes, int n_in,
                              void* d_out, int out_size) {
    const float* strains = (const float*)d_in[0];
    const float* dts     = (const float*)d_in[1];
    float* out           = (float*)d_out;

    const int B = 16384;
    maxwell_warp_scan_v3<<<B / WARPS_PER_BLOCK, NTHREADS>>>(strains, dts, out);
}

// round 5
// speedup vs baseline: 1.0565x; 1.0565x over previous
#include <cuda_runtime.h>

// Maxwell viscoelastic model, warp-parallel affine scan.
//   gamma_{t+1} = A_t*gamma_t + B_t,  A_t = 1-2*dt_t, B_t = 2*dt_t*eps_t
//   out_0 = 0 ; out_t = eps_t + 2*(eps_t - gamma_t)
//
// R3 dataflow (best so far): each lane owns 8 CONTIGUOUS timesteps (2 float4
// at quad indices 2*lane, 2*lane+1), ONE 5-round Kogge-Stone shuffle scan per
// 256 elements. The paired 16B-strided loads/stores jointly fill every 128B
// line, so no DRAM bytes are wasted. This round: slimmer scan epilogue
// (scalar-gamma shuffles instead of map shuffles: 12 SHFL/iter) and
// __launch_bounds__(256,5) to lift occupancy from 4 to 5 CTAs/SM.

#define TT   2048
#define EPL  8                         // elements per lane
#define EPI  (EPL * 32)                // 256 per warp-iteration
#define NITER (TT / EPI)               // 8
#define WARPS_PER_BLOCK 8
#define NTHREADS (WARPS_PER_BLOCK * 32)

__global__ __launch_bounds__(NTHREADS, 5)
void maxwell_warp_scan_v5(const float* __restrict__ eps_g,
                          const float* __restrict__ dt_g,
                          float* __restrict__ out_g) {
    const int lane = threadIdx.x & 31;
    const int warp = threadIdx.x >> 5;
    const int row  = blockIdx.x * WARPS_PER_BLOCK + warp;
    const size_t base = (size_t)row * TT;

    const float4* eps4 = reinterpret_cast<const float4*>(eps_g + base);
    const float4* dt4  = reinterpret_cast<const float4*>(dt_g  + base);
    float4*       out4 = reinterpret_cast<float4*>(out_g + base);

    float gamma_in = 0.0f;

    const int q0 = lane * 2;           // first quad owned by this lane

    // Prefetch iteration 0.
    float4 e0 = __ldcs(&eps4[q0]);
    float4 e1 = __ldcs(&eps4[q0 + 1]);
    float4 d0 = __ldcs(&dt4[q0]);
    float4 d1 = __ldcs(&dt4[q0 + 1]);

#pragma unroll 1
    for (int it = 0; it < NITER; ++it) {
        // Prefetch next iteration; in flight across the shuffle chain.
        float4 e0n, e1n, d0n, d1n;
        if (it + 1 < NITER) {
            const int qn = (it + 1) * 64 + q0;
            e0n = __ldcs(&eps4[qn]);
            e1n = __ldcs(&eps4[qn + 1]);
            d0n = __ldcs(&dt4[qn]);
            d1n = __ldcs(&dt4[qn + 1]);
        }

        const float ee[EPL] = {e0.x, e0.y, e0.z, e0.w, e1.x, e1.y, e1.z, e1.w};
        float td[EPL] = {d0.x + d0.x, d0.y + d0.y, d0.z + d0.z, d0.w + d0.w,
                         d1.x + d1.x, d1.y + d1.y, d1.z + d1.z, d1.w + d1.w};

        // Lane-local compose of 8 affine maps: (A,B) = m7 o ... o m0.
        float A = 1.0f - td[0];
        float B = td[0] * ee[0];
#pragma unroll
        for (int k = 1; k < EPL; ++k) {
            const float Ak = 1.0f - td[k];
            const float Bk = td[k] * ee[k];
            B = fmaf(Ak, B, Bk);
            A = Ak * A;
        }

        // Inclusive Kogge-Stone scan of affine maps across the warp.
        float SA = A, SB = B;
#pragma unroll
        for (int dstep = 1; dstep < 32; dstep <<= 1) {
            const float pA = __shfl_up_sync(0xffffffffu, SA, dstep);
            const float pB = __shfl_up_sync(0xffffffffu, SB, dstep);
            if (lane >= dstep) {
                SB = fmaf(SA, pB, SB);
                SA = SA * pA;
            }
        }

        // Scalar-gamma epilogue: one shuffle for entry gamma, one for carry.
        const float g_incl = fmaf(SA, gamma_in, SB);   // gamma AFTER this lane
        float g = __shfl_up_sync(0xffffffffu, g_incl, 1);
        if (lane == 0) g = gamma_in;                   // gamma BEFORE this lane
        gamma_in = __shfl_sync(0xffffffffu, g_incl, 31);

        // Serial apply: t = eps-gamma; sigma = eps + 2t; gamma += 2dt*t.
        float ss[EPL];
#pragma unroll
        for (int k = 0; k < EPL; ++k) {
            const float t = ee[k] - g;
            ss[k] = fmaf(2.0f, t, ee[k]);
            g = fmaf(td[k], t, g);
        }

        if (it == 0 && lane == 0) ss[0] = 0.0f;        // out[0] = 0

        const int qo = it * 64 + q0;
        __stcs(&out4[qo],     make_float4(ss[0], ss[1], ss[2], ss[3]));
        __stcs(&out4[qo + 1], make_float4(ss[4], ss[5], ss[6], ss[7]));

        if (it + 1 < NITER) { e0 = e0n; e1 = e1n; d0 = d0n; d1 = d1n; }
    }
}

extern "C" void kernel_launch(void* const* d_in, const int* in_sizes, int n_in,
                              void* d_out, int out_size) {
    const float* strains = (const float*)d_in[0];
    const float* dts     = (const float*)d_in[1];
    float* out           = (float*)d_out;

    const int B = 16384;
    maxwell_warp_scan_v5<<<B / WARPS_PER_BLOCK, NTHREADS>>>(strains, dts, out);
}

// round 7
// speedup vs baseline: 1.0570x; 1.0005x over previous
#include <cuda_runtime.h>
#include <cstdint>

// Maxwell viscoelastic model, warp-parallel affine scan with a warp-private
// cp.async (LDGSTS) pipeline.
//   gamma_{t+1} = A_t*gamma_t + B_t,  A_t = 1-2*dt_t, B_t = 2*dt_t*eps_t
//   out_0 = 0 ; out_t = eps_t + 2*(eps_t - gamma_t)
//
// Each warp owns one row; 256 timesteps per iteration (8 iters).
// eps/dt staged global->smem with cp.async.cg 16B (dense, coalesced, no
// destination registers -> MLP independent of register budget).
// Depth-3 warp-private pipeline, no __syncthreads.
//
// R6 bug fix: cp.async groups are counted PER THREAD; the tail iterations
// stopped committing, so wait_group<DEPTH-1> became a no-op with 2 groups
// left and iterations 6,7 read unlanded data. Now every iteration commits a
// group (empty ones complete immediately), so exactly one group retires per
// wait, including the drain.

#define TT    2048
#define EPI   256
#define NITER (TT / EPI)               // 8
#define WPB   8                        // warps per block
#define NTHREADS (WPB * 32)
#define DEPTH 3                        // pipeline stages per warp

// Stage layout per warp: [0..63] eps quads, [64..127] dt quads (float4).
#define STAGE_Q 128

__device__ __forceinline__ void cp16(float4* smem_dst, const float4* gmem_src) {
    uint32_t sa = (uint32_t)__cvta_generic_to_shared(smem_dst);
    asm volatile("cp.async.cg.shared.global [%0], [%1], 16;\n"
                 :: "r"(sa), "l"(gmem_src));
}
__device__ __forceinline__ void cp_commit() {
    asm volatile("cp.async.commit_group;\n");
}
template <int N>
__device__ __forceinline__ void cp_wait() {
    asm volatile("cp.async.wait_group %0;\n" :: "n"(N));
}

__global__ __launch_bounds__(NTHREADS, 4)
void maxwell_cpasync_scan(const float* __restrict__ eps_g,
                          const float* __restrict__ dt_g,
                          float* __restrict__ out_g) {
    __shared__ float4 sbuf[WPB][DEPTH][STAGE_Q];   // 48 KB

    const int lane = threadIdx.x & 31;
    const int warp = threadIdx.x >> 5;
    const int row  = blockIdx.x * WPB + warp;
    const size_t base = (size_t)row * TT;

    const float4* eps4 = reinterpret_cast<const float4*>(eps_g + base);
    const float4* dt4  = reinterpret_cast<const float4*>(dt_g  + base);
    float4*       out4 = reinterpret_cast<float4*>(out_g + base);

    // Prologue: fill the pipeline (DEPTH stages, one group each).
#pragma unroll
    for (int s = 0; s < DEPTH; ++s) {
        const int qb = s * 64;                      // global quad base
        float4* st = sbuf[warp][s];
        cp16(&st[lane],           &eps4[qb + lane]);
        cp16(&st[lane + 32],      &eps4[qb + lane + 32]);
        cp16(&st[64 + lane],      &dt4[qb + lane]);
        cp16(&st[64 + lane + 32], &dt4[qb + lane + 32]);
        cp_commit();
    }

    float gamma_in = 0.0f;
    const int ql = 2 * lane;                        // lane's first quad

#pragma unroll 1
    for (int it = 0; it < NITER; ++it) {
        const int s = it % DEPTH;

        cp_wait<DEPTH - 1>();                       // oldest group landed
        __syncwarp();                               // ...for ALL lanes

        const float4* st = sbuf[warp][s];
        const float4 e0 = st[ql];
        const float4 e1 = st[ql + 1];
        const float4 d0 = st[64 + ql];
        const float4 d1 = st[64 + ql + 1];

        __syncwarp();                               // all lanes done reading

        // Refill this stage for iteration it+DEPTH.
        // ALWAYS commit so group accounting retires one group per wait,
        // even in the drain (empty groups complete immediately).
        if (it + DEPTH < NITER) {
            const int qb = (it + DEPTH) * 64;
            float4* stw = sbuf[warp][s];
            cp16(&stw[lane],           &eps4[qb + lane]);
            cp16(&stw[lane + 32],      &eps4[qb + lane + 32]);
            cp16(&stw[64 + lane],      &dt4[qb + lane]);
            cp16(&stw[64 + lane + 32], &dt4[qb + lane + 32]);
        }
        cp_commit();

        const float ee[8] = {e0.x, e0.y, e0.z, e0.w, e1.x, e1.y, e1.z, e1.w};
        const float td[8] = {d0.x + d0.x, d0.y + d0.y, d0.z + d0.z, d0.w + d0.w,
                             d1.x + d1.x, d1.y + d1.y, d1.z + d1.z, d1.w + d1.w};

        // Lane-local compose of 8 affine maps: (A,B) = m7 o ... o m0.
        float A = 1.0f - td[0];
        float B = td[0] * ee[0];
#pragma unroll
        for (int k = 1; k < 8; ++k) {
            const float Ak = 1.0f - td[k];
            const float Bk = td[k] * ee[k];
            B = fmaf(Ak, B, Bk);
            A = Ak * A;
        }

        // Inclusive Kogge-Stone scan of affine maps across the warp.
        float SA = A, SB = B;
#pragma unroll
        for (int dstep = 1; dstep < 32; dstep <<= 1) {
            const float pA = __shfl_up_sync(0xffffffffu, SA, dstep);
            const float pB = __shfl_up_sync(0xffffffffu, SB, dstep);
            if (lane >= dstep) {
                SB = fmaf(SA, pB, SB);
                SA = SA * pA;
            }
        }

        // Scalar-gamma epilogue: entry gamma + warp carry (2 shuffles).
        const float g_incl = fmaf(SA, gamma_in, SB);
        float g = __shfl_up_sync(0xffffffffu, g_incl, 1);
        if (lane == 0) g = gamma_in;
        gamma_in = __shfl_sync(0xffffffffu, g_incl, 31);

        // Apply: t = eps-gamma; sigma = eps + 2t; gamma += 2dt*t.
        float ss[8];
#pragma unroll
        for (int k = 0; k < 8; ++k) {
            const float t = ee[k] - g;
            ss[k] = fmaf(2.0f, t, ee[k]);
            g = fmaf(td[k], t, g);
        }

        if (it == 0 && lane == 0) ss[0] = 0.0f;     // out[0] = 0

        const int qo = it * 64 + ql;
        __stcs(&out4[qo],     make_float4(ss[0], ss[1], ss[2], ss[3]));
        __stcs(&out4[qo + 1], make_float4(ss[4], ss[5], ss[6], ss[7]));
    }
}

extern "C" void kernel_launch(void* const* d_in, const int* in_sizes, int n_in,
                              void* d_out, int out_size) {
    const float* strains = (const float*)d_in[0];
    const float* dts     = (const float*)d_in[1];
    float* out           = (float*)d_out;

    const int B = 16384;
    maxwell_cpasync_scan<<<B / WPB, NTHREADS>>>(strains, dts, out);
}